// round 8
// baseline (speedup 1.0000x reference)
#include <cuda_runtime.h>
#include <math.h>

#define TT 2048
#define DD 1024
#define NT 8192
#define KTOP 4

__device__ float2 g_Qhl[NT * 32];        // [row][k] (hi,lo)
__device__ float2 g_KThl[4 * 32 * TT];   // [b][k][t] (hi,lo)

__device__ __forceinline__ float2 tf_split(float x) {
    unsigned u; asm("cvt.rna.tf32.f32 %0, %1;" : "=r"(u) : "f"(x));
    float h = __uint_as_float(u);
    return make_float2(h, x - h);
}
__device__ __forceinline__ void mma8(float* c, unsigned a0, unsigned a1,
                                     unsigned a2, unsigned a3,
                                     unsigned b0, unsigned b1) {
    asm volatile(
        "mma.sync.aligned.m16n8k8.row.col.f32.tf32.tf32.f32 "
        "{%0,%1,%2,%3}, {%4,%5,%6,%7}, {%8,%9}, {%0,%1,%2,%3};"
        : "+f"(c[0]), "+f"(c[1]), "+f"(c[2]), "+f"(c[3])
        : "r"(a0), "r"(a1), "r"(a2), "r"(a3), "r"(b0), "r"(b1));
}
__device__ __forceinline__ void mma3(float* c, const float2* a, float2 b0, float2 b1) {
    unsigned ah0 = __float_as_uint(a[0].x), ah1 = __float_as_uint(a[1].x),
             ah2 = __float_as_uint(a[2].x), ah3 = __float_as_uint(a[3].x);
    mma8(c, ah0, ah1, ah2, ah3, __float_as_uint(b0.y), __float_as_uint(b1.y));
    mma8(c, __float_as_uint(a[0].y), __float_as_uint(a[1].y),
            __float_as_uint(a[2].y), __float_as_uint(a[3].y),
            __float_as_uint(b0.x), __float_as_uint(b1.x));
    mma8(c, ah0, ah1, ah2, ah3, __float_as_uint(b0.x), __float_as_uint(b1.x));
}
__device__ __forceinline__ void upd4(float* v, int* ix, float s, int si) {
    if (s > v[3]) {
        if (s > v[1]) {
            v[3] = v[2]; ix[3] = ix[2]; v[2] = v[1]; ix[2] = ix[1];
            if (s > v[0]) { v[1] = v[0]; ix[1] = ix[0]; v[0] = s; ix[0] = si; }
            else          { v[1] = s; ix[1] = si; }
        } else {
            if (s > v[2]) { v[3] = v[2]; ix[3] = ix[2]; v[2] = s; ix[2] = si; }
            else          { v[3] = s; ix[3] = si; }
        }
    }
}

// ---------------------------------------------------------------------------
// Kernel 1: projection (tf32x3). grid=128, 256 thr. 64 rows x 64 cols x K=1024.
// ---------------------------------------------------------------------------
__global__ __launch_bounds__(256) void proj_mma(
    const float* __restrict__ x, const float* __restrict__ Wq,
    const float* __restrict__ bq, const float* __restrict__ Wk,
    const float* __restrict__ bk)
{
    __shared__ float2 Xs[64][33];
    __shared__ float2 Ws[32][65];
    __shared__ float  sbias[64];

    const int tid = threadIdx.x, lane = tid & 31, warp = tid >> 5;
    const int g = lane >> 2, t = lane & 3;
    const int wm = warp >> 1, wn = warp & 1;
    const int row0 = blockIdx.x * 64;

    if (tid < 64) sbias[tid] = (tid < 32) ? bq[tid] : bk[tid - 32];

    const int srow = tid >> 2, skq = (tid & 3) * 8;
    const float* wrow = (srow < 32) ? (Wq + (size_t)srow * DD)
                                    : (Wk + (size_t)(srow - 32) * DD);
    const float* xrow = x + (size_t)(row0 + srow) * DD;

    float acc[4][4];
    #pragma unroll
    for (int i = 0; i < 4; i++)
        #pragma unroll
        for (int j = 0; j < 4; j++) acc[i][j] = 0.0f;

    for (int kt = 0; kt < 32; kt++) {
        const int kb = kt * 32;
        float4 xv0 = *(const float4*)&xrow[kb + skq];
        float4 xv1 = *(const float4*)&xrow[kb + skq + 4];
        float4 wv0 = *(const float4*)&wrow[kb + skq];
        float4 wv1 = *(const float4*)&wrow[kb + skq + 4];
        __syncthreads();
        Xs[srow][skq + 0] = tf_split(xv0.x); Xs[srow][skq + 1] = tf_split(xv0.y);
        Xs[srow][skq + 2] = tf_split(xv0.z); Xs[srow][skq + 3] = tf_split(xv0.w);
        Xs[srow][skq + 4] = tf_split(xv1.x); Xs[srow][skq + 5] = tf_split(xv1.y);
        Xs[srow][skq + 6] = tf_split(xv1.z); Xs[srow][skq + 7] = tf_split(xv1.w);
        Ws[skq + 0][srow] = tf_split(wv0.x); Ws[skq + 1][srow] = tf_split(wv0.y);
        Ws[skq + 2][srow] = tf_split(wv0.z); Ws[skq + 3][srow] = tf_split(wv0.w);
        Ws[skq + 4][srow] = tf_split(wv1.x); Ws[skq + 5][srow] = tf_split(wv1.y);
        Ws[skq + 6][srow] = tf_split(wv1.z); Ws[skq + 7][srow] = tf_split(wv1.w);
        __syncthreads();

        #pragma unroll
        for (int k8 = 0; k8 < 4; k8++) {
            const int kk = k8 * 8;
            float2 a[4];
            a[0] = Xs[wm * 16 + g][kk + t];
            a[1] = Xs[wm * 16 + g + 8][kk + t];
            a[2] = Xs[wm * 16 + g][kk + t + 4];
            a[3] = Xs[wm * 16 + g + 8][kk + t + 4];
            #pragma unroll
            for (int nt = 0; nt < 4; nt++) {
                const int c0 = wn * 32 + nt * 8 + g;
                mma3(acc[nt], a, Ws[kk + t][c0], Ws[kk + t + 4][c0]);
            }
        }
    }

    const int rA = row0 + wm * 16 + g, rB = rA + 8;
    const int bb = row0 >> 11;
    const int tA = rA & (TT - 1), tB = tA + 8;
    #pragma unroll
    for (int nt = 0; nt < 4; nt++) {
        const int c = wn * 32 + nt * 8 + 2 * t;
        #pragma unroll
        for (int h = 0; h < 2; h++) {
            const int cc = c + h;
            float2 sA = tf_split(acc[nt][h]     + sbias[cc]);
            float2 sB = tf_split(acc[nt][2 + h] + sbias[cc]);
            if (cc < 32) {
                g_Qhl[(size_t)rA * 32 + cc] = sA;
                g_Qhl[(size_t)rB * 32 + cc] = sB;
            } else {
                const int kc = cc - 32;
                g_KThl[((size_t)bb * 32 + kc) * TT + tA] = sA;
                g_KThl[((size_t)bb * 32 + kc) * TT + tB] = sB;
            }
        }
    }
}

// ---------------------------------------------------------------------------
// Kernel 2: similarity (tf32x3) + top-4 + fused gather/mean.
// grid=128, 256 thr. 64 rows x 2048 keys (32 tiles of 64).
// ---------------------------------------------------------------------------
__global__ __launch_bounds__(256) void sim_gather(
    const float* __restrict__ x, float* __restrict__ out)
{
    __shared__ float2 Qs[64][33];
    __shared__ float2 Kt[32][66];
    __shared__ float  Mv[64][8];
    __shared__ int    Mi[64][8];
    __shared__ __align__(16) int sel[64][4];

    const int tid = threadIdx.x, lane = tid & 31, warp = tid >> 5;
    const int g = lane >> 2, t = lane & 3;
    const int wm = warp >> 1, wn = warp & 1;
    const int row0 = blockIdx.x * 64;
    const int bb   = row0 >> 11;

    {   // stage Q once
        const int r = tid >> 2, kq = (tid & 3) * 8;
        const float2* src = &g_Qhl[(size_t)(row0 + r) * 32 + kq];
        #pragma unroll
        for (int i = 0; i < 8; i++) Qs[r][kq + i] = src[i];
    }

    float tvA[4], tvB[4]; int tiA[4], tiB[4];
    #pragma unroll
    for (int p = 0; p < 4; p++) {
        tvA[p] = tvB[p] = -INFINITY; tiA[p] = tiB[p] = 0;
    }

    const float2* Kb = &g_KThl[(size_t)bb * 32 * TT];
    const int sk = tid >> 3, sj = tid & 7;

    for (int tile = 0; tile < 32; tile++) {
        const int key0 = tile * 64;
        __syncthreads();    // Qs ready (1st) / previous Kt consumed
        {
            const float4* src = (const float4*)&Kb[(size_t)sk * TT + key0];
            float4* dst = (float4*)&Kt[sk][0];
            dst[sj]      = src[sj];
            dst[sj + 8]  = src[sj + 8];
            dst[sj + 16] = src[sj + 16];
            dst[sj + 24] = src[sj + 24];
        }
        __syncthreads();

        float acc[4][4];
        #pragma unroll
        for (int i = 0; i < 4; i++)
            #pragma unroll
            for (int j = 0; j < 4; j++) acc[i][j] = 0.0f;

        #pragma unroll
        for (int k8 = 0; k8 < 4; k8++) {
            const int kk = k8 * 8;
            float2 a[4];
            a[0] = Qs[wm * 16 + g][kk + t];
            a[1] = Qs[wm * 16 + g + 8][kk + t];
            a[2] = Qs[wm * 16 + g][kk + t + 4];
            a[3] = Qs[wm * 16 + g + 8][kk + t + 4];
            #pragma unroll
            for (int nt = 0; nt < 4; nt++) {
                const int c0 = wn * 32 + nt * 8 + g;
                mma3(acc[nt], a, Kt[kk + t][c0], Kt[kk + t + 4][c0]);
            }
        }

        #pragma unroll
        for (int nt = 0; nt < 4; nt++) {
            const int idx = key0 + wn * 32 + nt * 8 + 2 * t;
            upd4(tvA, tiA, acc[nt][0], idx);
            upd4(tvA, tiA, acc[nt][1], idx + 1);
            upd4(tvB, tiB, acc[nt][2], idx);
            upd4(tvB, tiB, acc[nt][3], idx + 1);
        }
    }

    // merge across the 4 lanes (t) sharing each row — snapshot then insert
    #pragma unroll
    for (int off = 1; off <= 2; off <<= 1) {
        float ov[4]; int oi[4];
        #pragma unroll
        for (int p = 0; p < 4; p++) {
            ov[p] = __shfl_xor_sync(0xFFFFFFFFu, tvA[p], off);
            oi[p] = __shfl_xor_sync(0xFFFFFFFFu, tiA[p], off);
        }
        #pragma unroll
        for (int p = 0; p < 4; p++) upd4(tvA, tiA, ov[p], oi[p]);
        #pragma unroll
        for (int p = 0; p < 4; p++) {
            ov[p] = __shfl_xor_sync(0xFFFFFFFFu, tvB[p], off);
            oi[p] = __shfl_xor_sync(0xFFFFFFFFu, tiB[p], off);
        }
        #pragma unroll
        for (int p = 0; p < 4; p++) upd4(tvB, tiB, ov[p], oi[p]);
    }

    if (t == 0) {
        const int rA = wm * 16 + g, rB = rA + 8;
        #pragma unroll
        for (int p = 0; p < 4; p++) {
            Mv[rA][wn * 4 + p] = tvA[p]; Mi[rA][wn * 4 + p] = tiA[p];
            Mv[rB][wn * 4 + p] = tvB[p]; Mi[rB][wn * 4 + p] = tiB[p];
        }
    }
    __syncthreads();

    if (tid < 64) {
        float cv[8]; int ci[8];
        #pragma unroll
        for (int k = 0; k < 8; k++) { cv[k] = Mv[tid][k]; ci[k] = Mi[tid][k]; }
        #pragma unroll
        for (int p = 0; p < KTOP; p++) {
            int best = 0;
            #pragma unroll
            for (int k = 1; k < 8; k++)
                if (cv[k] > cv[best]) best = k;
            sel[tid][p] = ci[best];
            cv[best] = -INFINITY;
        }
    }
    __syncthreads();

    // fused gather + mean: warp per row, 8 rows per warp
    const float4* xb4 = (const float4*)(x + (size_t)bb * TT * DD);
    float4* out4 = (float4*)out;
    #pragma unroll
    for (int rr = 0; rr < 8; rr++) {
        const int rl = warp * 8 + rr;
        int4 iv = *(const int4*)&sel[rl][0];
        const float4* n0 = xb4 + (size_t)iv.x * 256;
        const float4* n1 = xb4 + (size_t)iv.y * 256;
        const float4* n2 = xb4 + (size_t)iv.z * 256;
        const float4* n3 = xb4 + (size_t)iv.w * 256;
        float4* o4 = out4 + (size_t)(row0 + rl) * 256;
        #pragma unroll
        for (int j = 0; j < 8; j++) {
            int c = lane + j * 32;
            float4 A = n0[c], B = n1[c], C = n2[c], D = n3[c];
            float4 o;
            o.x = (A.x + B.x + C.x + D.x) * 0.25f;
            o.y = (A.y + B.y + C.y + D.y) * 0.25f;
            o.z = (A.z + B.z + C.z + D.z) * 0.25f;
            o.w = (A.w + B.w + C.w + D.w) * 0.25f;
            o4[c] = o;
        }
    }
}

// ---------------------------------------------------------------------------
extern "C" void kernel_launch(void* const* d_in, const int* in_sizes, int n_in,
                              void* d_out, int out_size)
{
    const float* x  = (const float*)d_in[0];
    const float* Wq = (const float*)d_in[1];
    const float* bq = (const float*)d_in[2];
    const float* Wk = (const float*)d_in[3];
    const float* bk = (const float*)d_in[4];
    float* out = (float*)d_out;

    proj_mma<<<128, 256>>>(x, Wq, bq, Wk, bk);
    sim_gather<<<128, 256>>>(x, out);
}